// round 13
// baseline (speedup 1.0000x reference)
#include <cuda_runtime.h>
#include <cuda_fp16.h>

#define N_NODES_MAX 100000
#define E_MAX 1600000
#define IN_CH 128
#define HID 64
#define N_CLASSES 16
#define N_GRAPHS 64

// Scratch (device globals; no allocation allowed).
__device__ __align__(256) float  g_dis[N_NODES_MAX];                 // deg -> rsqrt(deg)
__device__ __align__(256) __half g_bufA[(size_t)N_NODES_MAX * HID];  // 12.8 MB (gemm out, fp16)
__device__ __align__(256) __half g_bufB[(size_t)N_NODES_MAX * HID];  // 12.8 MB (layer out, fp16)
__device__ __align__(256) float  g_pool[N_GRAPHS * HID];
__device__ __align__(256) float  g_cnt[N_GRAPHS];
// CSR by destination
__device__ __align__(256) int    g_cnt_i[N_NODES_MAX];
__device__ __align__(256) int    g_rowtmp[N_NODES_MAX];
__device__ __align__(256) int    g_rowptr[N_NODES_MAX + 1];
__device__ __align__(256) int    g_fill[N_NODES_MAX];
__device__ __align__(256) int    g_bsums[128];
__device__ __align__(256) int2   g_edge[E_MAX];                      // {src, bits(w)}

// ---------------- init: deg=1 (self loop), counts=0, pool zero ----------------
__global__ void k_init(int N) {
    int i = blockIdx.x * blockDim.x + threadIdx.x;
    if (i < N) { g_dis[i] = 1.0f; g_cnt_i[i] = 0; }
    if (i < N_GRAPHS * HID) g_pool[i] = 0.f;
    if (i < N_GRAPHS) g_cnt[i] = 0.f;
}

// ---------------- per-edge: count + weighted degree ----------------
__global__ void k_count_deg(const int* __restrict__ ei,
                            const float* __restrict__ ew, int E) {
    int e = blockIdx.x * blockDim.x + threadIdx.x;
    if (e < E) {
        int d = ei[E + e];
        atomicAdd(&g_cnt_i[d], 1);
        atomicAdd(&g_dis[d], ew[e]);
    }
}

// ---------------- prefix scan ----------------
__global__ __launch_bounds__(1024) void k_scan1(int N) {
    __shared__ int sh[1024];
    int i = blockIdx.x * 1024 + threadIdx.x;
    int v = (i < N) ? g_cnt_i[i] : 0;
    sh[threadIdx.x] = v;
    __syncthreads();
    for (int off = 1; off < 1024; off <<= 1) {
        int t = (threadIdx.x >= off) ? sh[threadIdx.x - off] : 0;
        __syncthreads();
        sh[threadIdx.x] += t;
        __syncthreads();
    }
    if (i < N) g_rowtmp[i] = sh[threadIdx.x] - v;  // exclusive
    if (threadIdx.x == 1023) g_bsums[blockIdx.x] = sh[1023];
}

// rowptr = rowtmp + block-sum prefix (re-derived per block in smem);
// also fill cursor init and dis=rsqrt(deg).
__global__ void k_scan3(int N, int E, int nb) {
    __shared__ int sh[128];
    int t = threadIdx.x;
    if (t < nb) sh[t] = g_bsums[t];
    __syncthreads();
    if (t == 0) {
        int run = 0;
        for (int j = 0; j < nb; j++) { int c = sh[j]; sh[j] = run; run += c; }
    }
    __syncthreads();
    int i = blockIdx.x * blockDim.x + t;
    if (i < N) {
        int rp = g_rowtmp[i] + sh[i >> 10];
        g_rowptr[i] = rp;
        g_fill[i] = rp;
        g_dis[i] = rsqrtf(g_dis[i]);
    }
    if (i == 0) g_rowptr[N] = E;
}

// ---------------- fill CSR: edge -> slot ----------------
__global__ void k_fill(const int* __restrict__ ei,
                       const float* __restrict__ ew, int E) {
    int e = blockIdx.x * blockDim.x + threadIdx.x;
    if (e < E) {
        int d = ei[E + e];
        int slot = atomicAdd(&g_fill[d], 1);
        g_edge[slot] = make_int2(ei[e], __float_as_int(ew[e]));
    }
}

// ---------------- tensor-core GEMM: bufA = half( (X @ W) * dis[row] ) ----------------
// 128-row tile per block, 256 threads = 8 warps, each warp 16 rows x 64 cols.
// mma.sync.m16n8k16 fp16 x fp16 -> fp32. X/W converted to fp16 in smem.
// src==0: X = Xf (fp32, input features). src==1: X = g_bufB (fp16, prev layer).
template <int K>
__global__ __launch_bounds__(256) void k_gemm_tc(const float* __restrict__ Xf,
                                                 const float* __restrict__ W,
                                                 int N, int src) {
    const int SX = 72;  // smem stride (halves); 72*2B=144B -> conflict-free quad access
    __shared__ __half Xh[128 * SX];
    __shared__ __half Wh[64 * SX];

    int t = threadIdx.x;
    int rowbase = blockIdx.x * 128;
    int lane = t & 31;
    int gID = lane >> 2;   // 0..7
    int t4 = lane & 3;     // 0..3
    int m_local = (t >> 5) * 16;

    float acc[8][4] = {};

    for (int kc = 0; kc < K; kc += 64) {
        // load X chunk: 128 rows x 64 halves (2048 x uint2)
        for (int f = t; f < 2048; f += 256) {
            int r = f >> 4;            // 16 uint2 per row
            int q = (f & 15) << 2;     // half offset 0..60
            int row = rowbase + r;
            uint2 hv = make_uint2(0u, 0u);
            if (row < N) {
                if (src == 0) {
                    float4 v = *(const float4*)(Xf + (size_t)row * K + kc + q);
                    __half2 p0 = __floats2half2_rn(v.x, v.y);
                    __half2 p1 = __floats2half2_rn(v.z, v.w);
                    hv.x = *(unsigned*)&p0;
                    hv.y = *(unsigned*)&p1;
                } else {
                    hv = *(const uint2*)(g_bufB + (size_t)row * K + kc + q);
                }
            }
            *(uint2*)&Xh[r * SX + q] = hv;
        }
        // load W chunk transposed: Wh[n][k] (column-major K x 64)
        for (int f = t; f < 4096; f += 256) {
            int kl = f >> 6;
            int c = f & 63;
            Wh[c * SX + kl] = __float2half(W[(size_t)(kc + kl) * 64 + c]);
        }
        __syncthreads();

#pragma unroll
        for (int kk = 0; kk < 64; kk += 16) {
            unsigned a0 = *(unsigned*)&Xh[(m_local + gID) * SX + kk + t4 * 2];
            unsigned a1 = *(unsigned*)&Xh[(m_local + gID + 8) * SX + kk + t4 * 2];
            unsigned a2 = *(unsigned*)&Xh[(m_local + gID) * SX + kk + 8 + t4 * 2];
            unsigned a3 = *(unsigned*)&Xh[(m_local + gID + 8) * SX + kk + 8 + t4 * 2];
#pragma unroll
            for (int j = 0; j < 8; j++) {
                int n = j * 8 + gID;
                unsigned b0 = *(unsigned*)&Wh[n * SX + kk + t4 * 2];
                unsigned b1 = *(unsigned*)&Wh[n * SX + kk + 8 + t4 * 2];
                asm volatile(
                    "mma.sync.aligned.m16n8k16.row.col.f32.f16.f16.f32 "
                    "{%0,%1,%2,%3}, {%4,%5,%6,%7}, {%8,%9}, {%0,%1,%2,%3};"
                    : "+f"(acc[j][0]), "+f"(acc[j][1]), "+f"(acc[j][2]), "+f"(acc[j][3])
                    : "r"(a0), "r"(a1), "r"(a2), "r"(a3), "r"(b0), "r"(b1));
            }
        }
        __syncthreads();
    }

    // epilogue: scale by dis, store fp16
    int r0 = rowbase + m_local + gID;
    int r1 = r0 + 8;
    if (r0 < N) {
        float ds = g_dis[r0];
#pragma unroll
        for (int j = 0; j < 8; j++) {
            __half2 h = __floats2half2_rn(acc[j][0] * ds, acc[j][1] * ds);
            *(__half2*)&g_bufA[(size_t)r0 * HID + j * 8 + t4 * 2] = h;
        }
    }
    if (r1 < N) {
        float ds = g_dis[r1];
#pragma unroll
        for (int j = 0; j < 8; j++) {
            __half2 h = __floats2half2_rn(acc[j][2] * ds, acc[j][3] * ds);
            *(__half2*)&g_bufA[(size_t)r1 * HID + j * 8 + t4 * 2] = h;
        }
    }
}

// ---------------- gather + dis + bias + relu (pull-mode, depth-2 pipeline) ----------------
// One warp per node, 32 lanes x half2 (128B/node = 1 L2 line). bufA(fp16) -> bufB(fp16).
// 4 edge records prefetched while 4 feature gathers are in flight.
__global__ __launch_bounds__(256) void k_gather(const float* __restrict__ bias, int N) {
    int node = (blockIdx.x * 256 + threadIdx.x) >> 5;
    if (node >= N) return;
    int lane = threadIdx.x & 31;

    const __half2* G = (const __half2*)g_bufA;
    int base = node * 32 + lane;
    float2 acc = __half22float2(G[base]);

    int k = __ldg(&g_rowptr[node]);
    int s1 = __ldg(&g_rowptr[node + 1]);

    int2 e0, e1, e2, e3;
    bool have4 = (k + 3 < s1);
    if (have4) {
        e0 = g_edge[k];     e1 = g_edge[k + 1];
        e2 = g_edge[k + 2]; e3 = g_edge[k + 3];
    }
    while (have4) {
        int2 c0 = e0, c1 = e1, c2 = e2, c3 = e3;
        k += 4;
        have4 = (k + 3 < s1);
        if (have4) {  // prefetch next quad while current gathers fly
            e0 = g_edge[k];     e1 = g_edge[k + 1];
            e2 = g_edge[k + 2]; e3 = g_edge[k + 3];
        }
        float2 v0 = __half22float2(G[c0.x * 32 + lane]);
        float2 v1 = __half22float2(G[c1.x * 32 + lane]);
        float2 v2 = __half22float2(G[c2.x * 32 + lane]);
        float2 v3 = __half22float2(G[c3.x * 32 + lane]);
        float w0 = __int_as_float(c0.y);
        float w1 = __int_as_float(c1.y);
        float w2 = __int_as_float(c2.y);
        float w3 = __int_as_float(c3.y);
        acc.x = fmaf(w0, v0.x, acc.x); acc.y = fmaf(w0, v0.y, acc.y);
        acc.x = fmaf(w1, v1.x, acc.x); acc.y = fmaf(w1, v1.y, acc.y);
        acc.x = fmaf(w2, v2.x, acc.x); acc.y = fmaf(w2, v2.y, acc.y);
        acc.x = fmaf(w3, v3.x, acc.x); acc.y = fmaf(w3, v3.y, acc.y);
    }
    // remainder: 0..3 edges, paired to keep 2 in flight
    if (k + 1 < s1) {
        int2 c0 = g_edge[k];
        int2 c1 = g_edge[k + 1];
        float2 v0 = __half22float2(G[c0.x * 32 + lane]);
        float2 v1 = __half22float2(G[c1.x * 32 + lane]);
        float w0 = __int_as_float(c0.y);
        float w1 = __int_as_float(c1.y);
        acc.x = fmaf(w0, v0.x, acc.x); acc.y = fmaf(w0, v0.y, acc.y);
        acc.x = fmaf(w1, v1.x, acc.x); acc.y = fmaf(w1, v1.y, acc.y);
        k += 2;
    }
    if (k < s1) {
        int2 c0 = g_edge[k];
        float2 v0 = __half22float2(G[c0.x * 32 + lane]);
        float w0 = __int_as_float(c0.y);
        acc.x = fmaf(w0, v0.x, acc.x); acc.y = fmaf(w0, v0.y, acc.y);
    }

    float ds = g_dis[node];
    float bx = bias[lane * 2];
    float by = bias[lane * 2 + 1];
    float ox = fmaf(ds, acc.x, bx);
    float oy = fmaf(ds, acc.y, by);
    ox = ox > 0.f ? ox : 0.f;
    oy = oy > 0.f ? oy : 0.f;
    ((__half2*)g_bufB)[base] = __floats2half2_rn(ox, oy);
}

// ---------------- pooling (256-row chunks) ----------------
#define POOL_CHUNK 256
__global__ __launch_bounds__(256) void k_pool(const int* __restrict__ batch, int N) {
    int base = blockIdx.x * POOL_CHUNK;
    int c = threadIdx.x & 63;
    int r0 = threadIdx.x >> 6;  // 0..3
    int end = base + POOL_CHUNK;
    if (end > N) end = N;

    float s = 0.f, n = 0.f;
    int cur = -1;
    for (int i = base + r0; i < end; i += 4) {
        int gi = batch[i];
        if (gi != cur) {
            if (cur >= 0) {
                atomicAdd(g_pool + cur * 64 + c, s);
                if (c == 0) atomicAdd(g_cnt + cur, n);
            }
            cur = gi; s = 0.f; n = 0.f;
        }
        s += __half2float(g_bufB[(size_t)i * HID + c]);
        n += 1.f;
    }
    if (cur >= 0) {
        atomicAdd(g_pool + cur * 64 + c, s);
        if (c == 0) atomicAdd(g_cnt + cur, n);
    }
}

// ---------------- head ----------------
__global__ void k_head(const float* __restrict__ Wl, const float* __restrict__ bl,
                       float* __restrict__ out) {
    int t = threadIdx.x;
    if (t >= N_GRAPHS * N_CLASSES) return;
    int g = t >> 4;
    int j = t & 15;
    float inv = 1.f / fmaxf(g_cnt[g], 1.f);
    float a = bl[j];
#pragma unroll
    for (int c = 0; c < 64; c++)
        a = fmaf(g_pool[g * 64 + c] * inv, Wl[c * 16 + j], a);
    out[t] = a;
}

// ---------------- launch ----------------
extern "C" void kernel_launch(void* const* d_in, const int* in_sizes, int n_in,
                              void* d_out, int out_size) {
    const float* x = (const float*)d_in[0];
    const int* ei = (const int*)d_in[1];      // int32 (JAX x64 disabled)
    const float* ew = (const float*)d_in[2];
    const int* batch = (const int*)d_in[3];   // int32
    const float* W1 = (const float*)d_in[4];
    const float* b1 = (const float*)d_in[5];
    const float* W2 = (const float*)d_in[6];
    const float* b2 = (const float*)d_in[7];
    const float* Wl = (const float*)d_in[8];
    const float* bl = (const float*)d_in[9];
    float* out = (float*)d_out;

    int N = in_sizes[0] / IN_CH;   // 100000
    int E = in_sizes[2];           // 1600000

    int tb = 256;
    int nblk = (N + tb - 1) / tb;
    int eblk = (E + tb - 1) / tb;
    int nb_scan = (N + 1023) / 1024;

    // ---- CSR build + degree ----
    k_init<<<nblk, tb>>>(N);
    k_count_deg<<<eblk, tb>>>(ei, ew, E);
    k_scan1<<<nb_scan, 1024>>>(N);
    k_scan3<<<nblk, tb>>>(N, E, nb_scan);
    k_fill<<<eblk, tb>>>(ei, ew, E);

    int gemm_blocks = (N + 127) / 128;
    int gather_blocks = (N * 32 + tb - 1) / tb;

    // layer 1
    k_gemm_tc<IN_CH><<<gemm_blocks, tb>>>(x, W1, N, 0);   // A = half((x@W1)*dis)
    k_gather<<<gather_blocks, tb>>>(b1, N);               // B = relu(dis*(agg A) + b1)

    // layer 2
    k_gemm_tc<HID><<<gemm_blocks, tb>>>(x, W2, N, 1);     // A = half((B@W2)*dis)
    k_gather<<<gather_blocks, tb>>>(b2, N);               // B = relu(dis*(agg A) + b2)

    // pooling + head
    k_pool<<<(N + POOL_CHUNK - 1) / POOL_CHUNK, tb>>>(batch, N);
    k_head<<<1, 1024>>>(Wl, bl, out);
}

// round 14
// speedup vs baseline: 1.1216x; 1.1216x over previous
#include <cuda_runtime.h>
#include <cuda_fp16.h>

#define N_NODES_MAX 100000
#define E_MAX 1600000
#define IN_CH 128
#define HID 64
#define N_CLASSES 16
#define N_GRAPHS 64

// Scratch (device globals; no allocation allowed).
__device__ __align__(256) float  g_dis[N_NODES_MAX];                 // deg -> rsqrt(deg)
__device__ __align__(256) __half g_bufA[(size_t)N_NODES_MAX * HID];  // 12.8 MB (gemm out, fp16)
__device__ __align__(256) __half g_bufB[(size_t)N_NODES_MAX * HID];  // 12.8 MB (layer out, fp16)
__device__ __align__(256) float  g_pool[N_GRAPHS * HID];
__device__ __align__(256) float  g_cnt[N_GRAPHS];
// CSR by destination
__device__ __align__(256) int    g_cnt_i[N_NODES_MAX];
__device__ __align__(256) int    g_rowtmp[N_NODES_MAX];
__device__ __align__(256) int    g_rowptr[N_NODES_MAX + 1];
__device__ __align__(256) int    g_fill[N_NODES_MAX];
__device__ __align__(256) int    g_bsums[128];
__device__ __align__(256) int2   g_edge[E_MAX];                      // {src, bits(ew*dis[src])}

// ---------------- init: deg=1 (self loop), counts=0, pool zero ----------------
__global__ void k_init(int N) {
    int i = blockIdx.x * blockDim.x + threadIdx.x;
    if (i < N) { g_dis[i] = 1.0f; g_cnt_i[i] = 0; }
    if (i < N_GRAPHS * HID) g_pool[i] = 0.f;
    if (i < N_GRAPHS) g_cnt[i] = 0.f;
}

// ---------------- per-edge: count + weighted degree ----------------
__global__ void k_count_deg(const int* __restrict__ ei,
                            const float* __restrict__ ew, int E) {
    int e = blockIdx.x * blockDim.x + threadIdx.x;
    if (e < E) {
        int d = ei[E + e];
        atomicAdd(&g_cnt_i[d], 1);
        atomicAdd(&g_dis[d], ew[e]);
    }
}

// ---------------- prefix scan ----------------
__global__ __launch_bounds__(1024) void k_scan1(int N) {
    __shared__ int sh[1024];
    int i = blockIdx.x * 1024 + threadIdx.x;
    int v = (i < N) ? g_cnt_i[i] : 0;
    sh[threadIdx.x] = v;
    __syncthreads();
    for (int off = 1; off < 1024; off <<= 1) {
        int t = (threadIdx.x >= off) ? sh[threadIdx.x - off] : 0;
        __syncthreads();
        sh[threadIdx.x] += t;
        __syncthreads();
    }
    if (i < N) g_rowtmp[i] = sh[threadIdx.x] - v;  // exclusive
    if (threadIdx.x == 1023) g_bsums[blockIdx.x] = sh[1023];
}

// rowptr = rowtmp + block-sum prefix (re-derived per block in smem);
// also fill cursor init and dis=rsqrt(deg).
__global__ void k_scan3(int N, int E, int nb) {
    __shared__ int sh[128];
    int t = threadIdx.x;
    if (t < nb) sh[t] = g_bsums[t];
    __syncthreads();
    if (t == 0) {
        int run = 0;
        for (int j = 0; j < nb; j++) { int c = sh[j]; sh[j] = run; run += c; }
    }
    __syncthreads();
    int i = blockIdx.x * blockDim.x + t;
    if (i < N) {
        int rp = g_rowtmp[i] + sh[i >> 10];
        g_rowptr[i] = rp;
        g_fill[i] = rp;
        g_dis[i] = rsqrtf(g_dis[i]);
    }
    if (i == 0) g_rowptr[N] = E;
}

// ---------------- fill CSR: edge -> slot, weight folded with dis[src] ----------------
__global__ void k_fill(const int* __restrict__ ei,
                       const float* __restrict__ ew, int E) {
    int e = blockIdx.x * blockDim.x + threadIdx.x;
    if (e < E) {
        int s = ei[e];
        int d = ei[E + e];
        float w = ew[e] * g_dis[s];
        int slot = atomicAdd(&g_fill[d], 1);
        g_edge[slot] = make_int2(s, __float_as_int(w));
    }
}

// ---------------- tensor-core GEMM: bufA = half( X @ W )  (no dis — folded elsewhere) ----
// 128-row tile per block, 256 threads = 8 warps, each warp 16 rows x 64 cols.
// mma.sync.m16n8k16 fp16 x fp16 -> fp32. X/W converted to fp16 in smem.
// src==0: X = Xf (fp32, input features). src==1: X = g_bufB (fp16, prev layer).
template <int K>
__global__ __launch_bounds__(256) void k_gemm_tc(const float* __restrict__ Xf,
                                                 const float* __restrict__ W,
                                                 int N, int src) {
    const int SX = 72;  // smem stride (halves); 72*2B=144B -> conflict-free quad access
    __shared__ __half Xh[128 * SX];
    __shared__ __half Wh[64 * SX];

    int t = threadIdx.x;
    int rowbase = blockIdx.x * 128;
    int lane = t & 31;
    int gID = lane >> 2;   // 0..7
    int t4 = lane & 3;     // 0..3
    int m_local = (t >> 5) * 16;

    float acc[8][4] = {};

    for (int kc = 0; kc < K; kc += 64) {
        // load X chunk: 128 rows x 64 halves (2048 x uint2)
        for (int f = t; f < 2048; f += 256) {
            int r = f >> 4;            // 16 uint2 per row
            int q = (f & 15) << 2;     // half offset 0..60
            int row = rowbase + r;
            uint2 hv = make_uint2(0u, 0u);
            if (row < N) {
                if (src == 0) {
                    float4 v = *(const float4*)(Xf + (size_t)row * K + kc + q);
                    __half2 p0 = __floats2half2_rn(v.x, v.y);
                    __half2 p1 = __floats2half2_rn(v.z, v.w);
                    hv.x = *(unsigned*)&p0;
                    hv.y = *(unsigned*)&p1;
                } else {
                    hv = *(const uint2*)(g_bufB + (size_t)row * K + kc + q);
                }
            }
            *(uint2*)&Xh[r * SX + q] = hv;
        }
        // load W chunk transposed: Wh[n][k] (column-major K x 64)
        for (int f = t; f < 4096; f += 256) {
            int kl = f >> 6;
            int c = f & 63;
            Wh[c * SX + kl] = __float2half(W[(size_t)(kc + kl) * 64 + c]);
        }
        __syncthreads();

#pragma unroll
        for (int kk = 0; kk < 64; kk += 16) {
            unsigned a0 = *(unsigned*)&Xh[(m_local + gID) * SX + kk + t4 * 2];
            unsigned a1 = *(unsigned*)&Xh[(m_local + gID + 8) * SX + kk + t4 * 2];
            unsigned a2 = *(unsigned*)&Xh[(m_local + gID) * SX + kk + 8 + t4 * 2];
            unsigned a3 = *(unsigned*)&Xh[(m_local + gID + 8) * SX + kk + 8 + t4 * 2];
#pragma unroll
            for (int j = 0; j < 8; j++) {
                int n = j * 8 + gID;
                unsigned b0 = *(unsigned*)&Wh[n * SX + kk + t4 * 2];
                unsigned b1 = *(unsigned*)&Wh[n * SX + kk + 8 + t4 * 2];
                asm volatile(
                    "mma.sync.aligned.m16n8k16.row.col.f32.f16.f16.f32 "
                    "{%0,%1,%2,%3}, {%4,%5,%6,%7}, {%8,%9}, {%0,%1,%2,%3};"
                    : "+f"(acc[j][0]), "+f"(acc[j][1]), "+f"(acc[j][2]), "+f"(acc[j][3])
                    : "r"(a0), "r"(a1), "r"(a2), "r"(a3), "r"(b0), "r"(b1));
            }
        }
        __syncthreads();
    }

    // epilogue: store fp16 (no dis scaling)
    int r0 = rowbase + m_local + gID;
    int r1 = r0 + 8;
    if (r0 < N) {
#pragma unroll
        for (int j = 0; j < 8; j++) {
            __half2 h = __floats2half2_rn(acc[j][0], acc[j][1]);
            *(__half2*)&g_bufA[(size_t)r0 * HID + j * 8 + t4 * 2] = h;
        }
    }
    if (r1 < N) {
#pragma unroll
        for (int j = 0; j < 8; j++) {
            __half2 h = __floats2half2_rn(acc[j][2], acc[j][3]);
            *(__half2*)&g_bufA[(size_t)r1 * HID + j * 8 + t4 * 2] = h;
        }
    }
}

// ---------------- gather + dis + bias + relu (pull-mode, 2-wide pipeline) ----------------
// One warp per node, 32 lanes x half2. bufA(fp16) -> bufB(fp16).
// acc = dis[node]*h[node] + sum w'*h[src];  out = dis[node]*acc + b, relu.
__global__ __launch_bounds__(256) void k_gather(const float* __restrict__ bias, int N) {
    int node = (blockIdx.x * 256 + threadIdx.x) >> 5;
    if (node >= N) return;
    int lane = threadIdx.x & 31;

    const __half2* G = (const __half2*)g_bufA;
    int base = node * 32 + lane;
    float ds = g_dis[node];
    float2 self = __half22float2(G[base]);
    float2 acc;
    acc.x = ds * self.x;
    acc.y = ds * self.y;

    int k = __ldg(&g_rowptr[node]);
    int s1 = __ldg(&g_rowptr[node + 1]);

    int2 e0, e1;
    bool have2 = (k + 1 < s1);
    if (have2) { e0 = g_edge[k]; e1 = g_edge[k + 1]; }
    while (have2) {
        int2 c0 = e0, c1 = e1;
        k += 2;
        have2 = (k + 1 < s1);
        if (have2) { e0 = g_edge[k]; e1 = g_edge[k + 1]; }  // prefetch next pair
        float2 v0 = __half22float2(G[c0.x * 32 + lane]);
        float2 v1 = __half22float2(G[c1.x * 32 + lane]);
        float w0 = __int_as_float(c0.y);
        float w1 = __int_as_float(c1.y);
        acc.x = fmaf(w0, v0.x, acc.x); acc.y = fmaf(w0, v0.y, acc.y);
        acc.x = fmaf(w1, v1.x, acc.x); acc.y = fmaf(w1, v1.y, acc.y);
    }
    if (k < s1) {
        int2 c0 = g_edge[k];
        float2 v0 = __half22float2(G[c0.x * 32 + lane]);
        float w0 = __int_as_float(c0.y);
        acc.x = fmaf(w0, v0.x, acc.x); acc.y = fmaf(w0, v0.y, acc.y);
    }

    float bx = bias[lane * 2];
    float by = bias[lane * 2 + 1];
    float ox = fmaf(ds, acc.x, bx);
    float oy = fmaf(ds, acc.y, by);
    ox = ox > 0.f ? ox : 0.f;
    oy = oy > 0.f ? oy : 0.f;
    ((__half2*)g_bufB)[base] = __floats2half2_rn(ox, oy);
}

// ---------------- pooling (256-row chunks) ----------------
#define POOL_CHUNK 256
__global__ __launch_bounds__(256) void k_pool(const int* __restrict__ batch, int N) {
    int base = blockIdx.x * POOL_CHUNK;
    int c = threadIdx.x & 63;
    int r0 = threadIdx.x >> 6;  // 0..3
    int end = base + POOL_CHUNK;
    if (end > N) end = N;

    float s = 0.f, n = 0.f;
    int cur = -1;
    for (int i = base + r0; i < end; i += 4) {
        int gi = batch[i];
        if (gi != cur) {
            if (cur >= 0) {
                atomicAdd(g_pool + cur * 64 + c, s);
                if (c == 0) atomicAdd(g_cnt + cur, n);
            }
            cur = gi; s = 0.f; n = 0.f;
        }
        s += __half2float(g_bufB[(size_t)i * HID + c]);
        n += 1.f;
    }
    if (cur >= 0) {
        atomicAdd(g_pool + cur * 64 + c, s);
        if (c == 0) atomicAdd(g_cnt + cur, n);
    }
}

// ---------------- head ----------------
__global__ void k_head(const float* __restrict__ Wl, const float* __restrict__ bl,
                       float* __restrict__ out) {
    int t = threadIdx.x;
    if (t >= N_GRAPHS * N_CLASSES) return;
    int g = t >> 4;
    int j = t & 15;
    float inv = 1.f / fmaxf(g_cnt[g], 1.f);
    float a = bl[j];
#pragma unroll
    for (int c = 0; c < 64; c++)
        a = fmaf(g_pool[g * 64 + c] * inv, Wl[c * 16 + j], a);
    out[t] = a;
}

// ---------------- launch ----------------
extern "C" void kernel_launch(void* const* d_in, const int* in_sizes, int n_in,
                              void* d_out, int out_size) {
    const float* x = (const float*)d_in[0];
    const int* ei = (const int*)d_in[1];      // int32 (JAX x64 disabled)
    const float* ew = (const float*)d_in[2];
    const int* batch = (const int*)d_in[3];   // int32
    const float* W1 = (const float*)d_in[4];
    const float* b1 = (const float*)d_in[5];
    const float* W2 = (const float*)d_in[6];
    const float* b2 = (const float*)d_in[7];
    const float* Wl = (const float*)d_in[8];
    const float* bl = (const float*)d_in[9];
    float* out = (float*)d_out;

    int N = in_sizes[0] / IN_CH;   // 100000
    int E = in_sizes[2];           // 1600000

    // one-time side stream + events (host-side objects only; no device alloc)
    static cudaStream_t s_side = nullptr;
    static cudaEvent_t s_evF = nullptr, s_evJ = nullptr;
    if (!s_side) {
        cudaStreamCreateWithFlags(&s_side, cudaStreamNonBlocking);
        cudaEventCreateWithFlags(&s_evF, cudaEventDisableTiming);
        cudaEventCreateWithFlags(&s_evJ, cudaEventDisableTiming);
    }

    int tb = 256;
    int nblk = (N + tb - 1) / tb;
    int eblk = (E + tb - 1) / tb;
    int nb_scan = (N + 1023) / 1024;
    int gemm_blocks = (N + 127) / 128;
    int gather_blocks = (N * 32 + tb - 1) / tb;

    // ---- fork: GEMM1 (independent of CSR/dis) on side stream ----
    cudaEventRecord(s_evF, 0);
    cudaStreamWaitEvent(s_side, s_evF, 0);
    k_gemm_tc<IN_CH><<<gemm_blocks, tb, 0, s_side>>>(x, W1, N, 0);  // A = half(x@W1)
    cudaEventRecord(s_evJ, s_side);

    // ---- CSR build + degree on main stream (concurrent with GEMM1) ----
    k_init<<<nblk, tb>>>(N);
    k_count_deg<<<eblk, tb>>>(ei, ew, E);
    k_scan1<<<nb_scan, 1024>>>(N);
    k_scan3<<<nblk, tb>>>(N, E, nb_scan);
    k_fill<<<eblk, tb>>>(ei, ew, E);

    // ---- join: gather1 needs both CSR and GEMM1 ----
    cudaStreamWaitEvent(0, s_evJ, 0);

    // layer 1 aggregation
    k_gather<<<gather_blocks, tb>>>(b1, N);               // B = relu(dis*(dis*A + agg w'*A) + b1)

    // layer 2
    k_gemm_tc<HID><<<gemm_blocks, tb>>>(x, W2, N, 1);     // A = half(B@W2)
    k_gather<<<gather_blocks, tb>>>(b2, N);               // B = relu(... + b2)

    // pooling + head
    k_pool<<<(N + POOL_CHUNK - 1) / POOL_CHUNK, tb>>>(batch, N);
    k_head<<<1, 1024>>>(Wl, bl, out);
}

// round 15
// speedup vs baseline: 1.2181x; 1.0860x over previous
#include <cuda_runtime.h>
#include <cuda_fp16.h>

#define N_NODES_MAX 100000
#define E_MAX 1600000
#define IN_CH 128
#define HID 64
#define N_CLASSES 16
#define N_GRAPHS 64

// Scratch (device globals; no allocation allowed).
__device__ __align__(256) float  g_dis[N_NODES_MAX];                 // deg -> rsqrt(deg)
__device__ __align__(256) __half g_bufA[(size_t)N_NODES_MAX * HID];  // 12.8 MB (gemm out, fp16)
__device__ __align__(256) __half g_bufB[(size_t)N_NODES_MAX * HID];  // 12.8 MB (layer out, fp16)
__device__ __align__(256) float  g_pool[N_GRAPHS * HID];
__device__ __align__(256) float  g_cnt[N_GRAPHS];
// CSR by destination
__device__ __align__(256) int    g_cnt_i[N_NODES_MAX];
__device__ __align__(256) int    g_rowtmp[N_NODES_MAX];
__device__ __align__(256) int    g_rowptr[N_NODES_MAX + 1];
__device__ __align__(256) int    g_fill[N_NODES_MAX];
__device__ __align__(256) int    g_bsums[128];
__device__ __align__(256) int2   g_edge[E_MAX];                      // {src, bits(ew*dis[src])}

// ---------------- init: deg=1 (self loop), counts=0, pool zero ----------------
__global__ void k_init(int N) {
    int i = blockIdx.x * blockDim.x + threadIdx.x;
    if (i < N) { g_dis[i] = 1.0f; g_cnt_i[i] = 0; }
    if (i < N_GRAPHS * HID) g_pool[i] = 0.f;
    if (i < N_GRAPHS) g_cnt[i] = 0.f;
}

// ---------------- per-edge: count + weighted degree ----------------
__global__ void k_count_deg(const int* __restrict__ ei,
                            const float* __restrict__ ew, int E) {
    int e = blockIdx.x * blockDim.x + threadIdx.x;
    if (e < E) {
        int d = ei[E + e];
        atomicAdd(&g_cnt_i[d], 1);
        atomicAdd(&g_dis[d], ew[e]);
    }
}

// ---------------- prefix scan ----------------
__global__ __launch_bounds__(1024) void k_scan1(int N) {
    __shared__ int sh[1024];
    int i = blockIdx.x * 1024 + threadIdx.x;
    int v = (i < N) ? g_cnt_i[i] : 0;
    sh[threadIdx.x] = v;
    __syncthreads();
    for (int off = 1; off < 1024; off <<= 1) {
        int t = (threadIdx.x >= off) ? sh[threadIdx.x - off] : 0;
        __syncthreads();
        sh[threadIdx.x] += t;
        __syncthreads();
    }
    if (i < N) g_rowtmp[i] = sh[threadIdx.x] - v;  // exclusive
    if (threadIdx.x == 1023) g_bsums[blockIdx.x] = sh[1023];
}

// rowptr = rowtmp + block-sum prefix (re-derived per block in smem);
// also fill cursor init and dis=rsqrt(deg).
__global__ void k_scan3(int N, int E, int nb) {
    __shared__ int sh[128];
    int t = threadIdx.x;
    if (t < nb) sh[t] = g_bsums[t];
    __syncthreads();
    if (t == 0) {
        int run = 0;
        for (int j = 0; j < nb; j++) { int c = sh[j]; sh[j] = run; run += c; }
    }
    __syncthreads();
    int i = blockIdx.x * blockDim.x + t;
    if (i < N) {
        int rp = g_rowtmp[i] + sh[i >> 10];
        g_rowptr[i] = rp;
        g_fill[i] = rp;
        g_dis[i] = rsqrtf(g_dis[i]);
    }
    if (i == 0) g_rowptr[N] = E;
}

// ---------------- fill CSR: edge -> slot, weight folded with dis[src] ----------------
__global__ void k_fill(const int* __restrict__ ei,
                       const float* __restrict__ ew, int E) {
    int e = blockIdx.x * blockDim.x + threadIdx.x;
    if (e < E) {
        int s = ei[e];
        int d = ei[E + e];
        float w = ew[e] * g_dis[s];
        int slot = atomicAdd(&g_fill[d], 1);
        g_edge[slot] = make_int2(s, __float_as_int(w));
    }
}

// ---------------- tensor-core GEMM: bufA = half( X @ W )  (no dis — folded elsewhere) ----
// 128-row tile per block, 256 threads = 8 warps, each warp 16 rows x 64 cols.
// mma.sync.m16n8k16 fp16 x fp16 -> fp32. X/W converted to fp16 in smem.
// src==0: X = Xf (fp32, input features). src==1: X = g_bufB (fp16, prev layer).
template <int K>
__global__ __launch_bounds__(256) void k_gemm_tc(const float* __restrict__ Xf,
                                                 const float* __restrict__ W,
                                                 int N, int src) {
    const int SX = 72;  // smem stride (halves); 72*2B=144B -> conflict-free quad access
    __shared__ __half Xh[128 * SX];
    __shared__ __half Wh[64 * SX];

    int t = threadIdx.x;
    int rowbase = blockIdx.x * 128;
    int lane = t & 31;
    int gID = lane >> 2;   // 0..7
    int t4 = lane & 3;     // 0..3
    int m_local = (t >> 5) * 16;

    float acc[8][4] = {};

    for (int kc = 0; kc < K; kc += 64) {
        // load X chunk: 128 rows x 64 halves (2048 x uint2)
        for (int f = t; f < 2048; f += 256) {
            int r = f >> 4;            // 16 uint2 per row
            int q = (f & 15) << 2;     // half offset 0..60
            int row = rowbase + r;
            uint2 hv = make_uint2(0u, 0u);
            if (row < N) {
                if (src == 0) {
                    float4 v = *(const float4*)(Xf + (size_t)row * K + kc + q);
                    __half2 p0 = __floats2half2_rn(v.x, v.y);
                    __half2 p1 = __floats2half2_rn(v.z, v.w);
                    hv.x = *(unsigned*)&p0;
                    hv.y = *(unsigned*)&p1;
                } else {
                    hv = *(const uint2*)(g_bufB + (size_t)row * K + kc + q);
                }
            }
            *(uint2*)&Xh[r * SX + q] = hv;
        }
        // load W chunk transposed: Wh[n][k] (column-major K x 64)
        for (int f = t; f < 4096; f += 256) {
            int kl = f >> 6;
            int c = f & 63;
            Wh[c * SX + kl] = __float2half(W[(size_t)(kc + kl) * 64 + c]);
        }
        __syncthreads();

#pragma unroll
        for (int kk = 0; kk < 64; kk += 16) {
            unsigned a0 = *(unsigned*)&Xh[(m_local + gID) * SX + kk + t4 * 2];
            unsigned a1 = *(unsigned*)&Xh[(m_local + gID + 8) * SX + kk + t4 * 2];
            unsigned a2 = *(unsigned*)&Xh[(m_local + gID) * SX + kk + 8 + t4 * 2];
            unsigned a3 = *(unsigned*)&Xh[(m_local + gID + 8) * SX + kk + 8 + t4 * 2];
#pragma unroll
            for (int j = 0; j < 8; j++) {
                int n = j * 8 + gID;
                unsigned b0 = *(unsigned*)&Wh[n * SX + kk + t4 * 2];
                unsigned b1 = *(unsigned*)&Wh[n * SX + kk + 8 + t4 * 2];
                asm volatile(
                    "mma.sync.aligned.m16n8k16.row.col.f32.f16.f16.f32 "
                    "{%0,%1,%2,%3}, {%4,%5,%6,%7}, {%8,%9}, {%0,%1,%2,%3};"
                    : "+f"(acc[j][0]), "+f"(acc[j][1]), "+f"(acc[j][2]), "+f"(acc[j][3])
                    : "r"(a0), "r"(a1), "r"(a2), "r"(a3), "r"(b0), "r"(b1));
            }
        }
        __syncthreads();
    }

    // epilogue: store fp16 (no dis scaling)
    int r0 = rowbase + m_local + gID;
    int r1 = r0 + 8;
    if (r0 < N) {
#pragma unroll
        for (int j = 0; j < 8; j++) {
            __half2 h = __floats2half2_rn(acc[j][0], acc[j][1]);
            *(__half2*)&g_bufA[(size_t)r0 * HID + j * 8 + t4 * 2] = h;
        }
    }
    if (r1 < N) {
#pragma unroll
        for (int j = 0; j < 8; j++) {
            __half2 h = __floats2half2_rn(acc[j][2], acc[j][3]);
            *(__half2*)&g_bufA[(size_t)r1 * HID + j * 8 + t4 * 2] = h;
        }
    }
}

// ---------------- gather + dis + bias + relu (2 nodes/warp, 16 lanes each) ----------------
// Each 16-lane group owns one node; lane holds uint2 = 4 halves (full 128B row per group).
// Two independent 2-wide-pipelined chains per warp -> 2x concurrent latency chains.
// acc = dis[node]*h[node] + sum w'*h[src];  out = dis[node]*acc + b, relu.
__global__ __launch_bounds__(256) void k_gather(const float* __restrict__ bias, int N) {
    int gid = blockIdx.x * 256 + threadIdx.x;
    int node = gid >> 4;
    if (node >= N) return;
    int lane = threadIdx.x & 15;   // 0..15 within group

    const uint2* G = (const uint2*)g_bufA;   // 16 uint2 per node row
    int base = node * 16 + lane;
    float ds = g_dis[node];

    uint2 sv = G[base];
    float2 p0 = __half22float2(*(__half2*)&sv.x);
    float2 p1 = __half22float2(*(__half2*)&sv.y);
    float4 acc = make_float4(ds * p0.x, ds * p0.y, ds * p1.x, ds * p1.y);

    int k = __ldg(&g_rowptr[node]);
    int s1 = __ldg(&g_rowptr[node + 1]);

    int2 e0, e1;
    bool have2 = (k + 1 < s1);
    if (have2) { e0 = g_edge[k]; e1 = g_edge[k + 1]; }
    while (have2) {
        int2 c0 = e0, c1 = e1;
        k += 2;
        have2 = (k + 1 < s1);
        if (have2) { e0 = g_edge[k]; e1 = g_edge[k + 1]; }  // prefetch next pair
        uint2 u0 = G[c0.x * 16 + lane];
        uint2 u1 = G[c1.x * 16 + lane];
        float w0 = __int_as_float(c0.y);
        float w1 = __int_as_float(c1.y);
        float2 a0 = __half22float2(*(__half2*)&u0.x);
        float2 b0 = __half22float2(*(__half2*)&u0.y);
        float2 a1 = __half22float2(*(__half2*)&u1.x);
        float2 b1 = __half22float2(*(__half2*)&u1.y);
        acc.x = fmaf(w0, a0.x, acc.x); acc.y = fmaf(w0, a0.y, acc.y);
        acc.z = fmaf(w0, b0.x, acc.z); acc.w = fmaf(w0, b0.y, acc.w);
        acc.x = fmaf(w1, a1.x, acc.x); acc.y = fmaf(w1, a1.y, acc.y);
        acc.z = fmaf(w1, b1.x, acc.z); acc.w = fmaf(w1, b1.y, acc.w);
    }
    if (k < s1) {
        int2 c0 = g_edge[k];
        uint2 u0 = G[c0.x * 16 + lane];
        float w0 = __int_as_float(c0.y);
        float2 a0 = __half22float2(*(__half2*)&u0.x);
        float2 b0 = __half22float2(*(__half2*)&u0.y);
        acc.x = fmaf(w0, a0.x, acc.x); acc.y = fmaf(w0, a0.y, acc.y);
        acc.z = fmaf(w0, b0.x, acc.z); acc.w = fmaf(w0, b0.y, acc.w);
    }

    float4 bv = *(const float4*)(bias + lane * 4);
    float o0 = fmaf(ds, acc.x, bv.x);
    float o1 = fmaf(ds, acc.y, bv.y);
    float o2 = fmaf(ds, acc.z, bv.z);
    float o3 = fmaf(ds, acc.w, bv.w);
    o0 = o0 > 0.f ? o0 : 0.f;
    o1 = o1 > 0.f ? o1 : 0.f;
    o2 = o2 > 0.f ? o2 : 0.f;
    o3 = o3 > 0.f ? o3 : 0.f;
    __half2 h0 = __floats2half2_rn(o0, o1);
    __half2 h1 = __floats2half2_rn(o2, o3);
    uint2 ov;
    ov.x = *(unsigned*)&h0;
    ov.y = *(unsigned*)&h1;
    ((uint2*)g_bufB)[base] = ov;
}

// ---------------- pooling (256-row chunks) ----------------
#define POOL_CHUNK 256
__global__ __launch_bounds__(256) void k_pool(const int* __restrict__ batch, int N) {
    int base = blockIdx.x * POOL_CHUNK;
    int c = threadIdx.x & 63;
    int r0 = threadIdx.x >> 6;  // 0..3
    int end = base + POOL_CHUNK;
    if (end > N) end = N;

    float s = 0.f, n = 0.f;
    int cur = -1;
    for (int i = base + r0; i < end; i += 4) {
        int gi = batch[i];
        if (gi != cur) {
            if (cur >= 0) {
                atomicAdd(g_pool + cur * 64 + c, s);
                if (c == 0) atomicAdd(g_cnt + cur, n);
            }
            cur = gi; s = 0.f; n = 0.f;
        }
        s += __half2float(g_bufB[(size_t)i * HID + c]);
        n += 1.f;
    }
    if (cur >= 0) {
        atomicAdd(g_pool + cur * 64 + c, s);
        if (c == 0) atomicAdd(g_cnt + cur, n);
    }
}

// ---------------- head ----------------
__global__ void k_head(const float* __restrict__ Wl, const float* __restrict__ bl,
                       float* __restrict__ out) {
    int t = threadIdx.x;
    if (t >= N_GRAPHS * N_CLASSES) return;
    int g = t >> 4;
    int j = t & 15;
    float inv = 1.f / fmaxf(g_cnt[g], 1.f);
    float a = bl[j];
#pragma unroll
    for (int c = 0; c < 64; c++)
        a = fmaf(g_pool[g * 64 + c] * inv, Wl[c * 16 + j], a);
    out[t] = a;
}

// ---------------- launch ----------------
extern "C" void kernel_launch(void* const* d_in, const int* in_sizes, int n_in,
                              void* d_out, int out_size) {
    const float* x = (const float*)d_in[0];
    const int* ei = (const int*)d_in[1];      // int32 (JAX x64 disabled)
    const float* ew = (const float*)d_in[2];
    const int* batch = (const int*)d_in[3];   // int32
    const float* W1 = (const float*)d_in[4];
    const float* b1 = (const float*)d_in[5];
    const float* W2 = (const float*)d_in[6];
    const float* b2 = (const float*)d_in[7];
    const float* Wl = (const float*)d_in[8];
    const float* bl = (const float*)d_in[9];
    float* out = (float*)d_out;

    int N = in_sizes[0] / IN_CH;   // 100000
    int E = in_sizes[2];           // 1600000

    // one-time side stream + events (host-side objects only; no device alloc)
    static cudaStream_t s_side = nullptr;
    static cudaEvent_t s_evF = nullptr, s_evJ = nullptr;
    if (!s_side) {
        cudaStreamCreateWithFlags(&s_side, cudaStreamNonBlocking);
        cudaEventCreateWithFlags(&s_evF, cudaEventDisableTiming);
        cudaEventCreateWithFlags(&s_evJ, cudaEventDisableTiming);
    }

    int tb = 256;
    int nblk = (N + tb - 1) / tb;
    int eblk = (E + tb - 1) / tb;
    int nb_scan = (N + 1023) / 1024;
    int gemm_blocks = (N + 127) / 128;
    int gather_blocks = (N * 16 + tb - 1) / tb;

    // ---- fork: GEMM1 (independent of CSR/dis) on side stream ----
    cudaEventRecord(s_evF, 0);
    cudaStreamWaitEvent(s_side, s_evF, 0);
    k_gemm_tc<IN_CH><<<gemm_blocks, tb, 0, s_side>>>(x, W1, N, 0);  // A = half(x@W1)
    cudaEventRecord(s_evJ, s_side);

    // ---- CSR build + degree on main stream (concurrent with GEMM1) ----
    k_init<<<nblk, tb>>>(N);
    k_count_deg<<<eblk, tb>>>(ei, ew, E);
    k_scan1<<<nb_scan, 1024>>>(N);
    k_scan3<<<nblk, tb>>>(N, E, nb_scan);
    k_fill<<<eblk, tb>>>(ei, ew, E);

    // ---- join: gather1 needs both CSR and GEMM1 ----
    cudaStreamWaitEvent(0, s_evJ, 0);

    // layer 1 aggregation
    k_gather<<<gather_blocks, tb>>>(b1, N);               // B = relu(dis*(dis*A + agg w'*A) + b1)

    // layer 2
    k_gemm_tc<HID><<<gemm_blocks, tb>>>(x, W2, N, 1);     // A = half(B@W2)
    k_gather<<<gather_blocks, tb>>>(b2, N);               // B = relu(... + b2)

    // pooling + head
    k_pool<<<(N + POOL_CHUNK - 1) / POOL_CHUNK, tb>>>(batch, N);
    k_head<<<1, 1024>>>(Wl, bl, out);
}